// round 11
// baseline (speedup 1.0000x reference)
#include <cuda_runtime.h>
#include <cuda_fp16.h>
#include <cstring>
#include <cmath>

// ============================================================================
// CPAB activation (difw Tessellation, NC=16 cells, RADIUS=3, 10x5 integration)
//
// out[n,c] = f_c(x[n,c]) where f_c is piecewise-LINEAR in x0. Strategy:
//   1) host: B_BASIS = last 15 rows of Q from Householder LQ of the 17x32
//      constraint matrix (matches numpy dgesdd Path 4t null-space rows).
//   2) gpu:  build per-channel LUT with the exact reference integrator,
//      stored as half2 (d_i, d_{i+1}) displacement pairs: out = xv + lerp(d).
//      512 threads/block -> one serial integration chain per thread.
//   3) gpu:  float4 streaming pass, 32 channels (=128B) per block row,
//      4 wavefronts per LDG.128/STG.128, branch-free clamped lerp,
//      1024 thr/block, 65.7KB dynamic smem, 2 blocks/SM, single wave.
//      Launched with PROGRAMMATIC DEPENDENT LAUNCH: blocks spin up while the
//      build kernel is still running, then cudaGridDependencySynchronize()
//      before reading g_tabh (implicit trigger at build completion => full
//      memory visibility). Hides main-kernel launch latency behind build.
// ============================================================================

#define M_SAMP      512
#define TAB_W       (M_SAMP + 1)          // word stride per channel (odd)
#define CH_PER_BLK  32
#define MAX_C       256

struct BParam { float B[32][15]; };

// Packed displacement table: word i of channel c = half2(d_i, d_{i+1}).
__device__ __half2 g_tabh[MAX_C * TAB_W];

// ----------------------------------------------------------------------------
// Host: B_BASIS via Householder LQ (float64), matching LAPACK DGELQF/DORGLQ.
// ----------------------------------------------------------------------------
static void compute_basis(float Bout[32][15]) {
    const int nc = 16;
    const int m = nc + 1;      // 17
    const int n = 2 * nc;      // 32
    double A[17][32];
    std::memset(A, 0, sizeof(A));
    for (int k = 1; k < nc; k++) {
        double xk = (double)k / (double)nc;
        A[k - 1][2 * (k - 1)]     =  xk;
        A[k - 1][2 * (k - 1) + 1] =  1.0;
        A[k - 1][2 * k]           = -xk;
        A[k - 1][2 * k + 1]       = -1.0;
    }
    A[nc - 1][1]         = 1.0;
    A[nc][2 * (nc - 1)]  = 1.0;
    A[nc][2 * nc - 1]    = 1.0;

    double tau[17];
    for (int i = 0; i < m; i++) {
        double xn2 = 0.0;
        for (int j = i + 1; j < n; j++) xn2 += A[i][j] * A[i][j];
        double alpha = A[i][i];
        if (xn2 == 0.0) { tau[i] = 0.0; continue; }
        double beta = -copysign(sqrt(alpha * alpha + xn2), alpha);
        tau[i] = (beta - alpha) / beta;
        double s = 1.0 / (alpha - beta);
        for (int j = i + 1; j < n; j++) A[i][j] *= s;
        A[i][i] = beta;
        for (int r = i + 1; r < m; r++) {
            double w = A[r][i];
            for (int j = i + 1; j < n; j++) w += A[r][j] * A[i][j];
            w *= tau[i];
            A[r][i] -= w;
            for (int j = i + 1; j < n; j++) A[r][j] -= w * A[i][j];
        }
    }
    for (int t = 0; t < 15; t++) {
        double q[32];
        for (int j = 0; j < n; j++) q[j] = 0.0;
        q[m + t] = 1.0;
        for (int i = m - 1; i >= 0; i--) {
            if (tau[i] == 0.0) continue;
            double w = q[i];
            for (int j = i + 1; j < n; j++) w += A[i][j] * q[j];
            w *= tau[i];
            q[i] -= w;
            for (int j = i + 1; j < n; j++) q[j] -= w * A[i][j];
        }
        for (int j = 0; j < n; j++) Bout[j][t] = (float)q[j];
    }
}

// ----------------------------------------------------------------------------
// Device
// ----------------------------------------------------------------------------
__device__ __forceinline__ int cellf(float x) {
    int c = __float2int_rd(x * 16.0f);
    return min(max(c, 0), 15);
}

// One block per channel, 512 threads: a,b from theta @ B^T, exact reference
// integration -- one grid sample per thread (tid 0 also takes node 512).
__global__ void __launch_bounds__(512) build_tab_kernel(
        const float* __restrict__ theta,
        const int* __restrict__ time_p,
        float* __restrict__ theta_out,
        BParam Bp) {
    __shared__ float sa[16], sb[16], sE[16], sK[16];
    __shared__ float sd[M_SAMP + 1];        // displacements d_i (fp32)
    int c = blockIdx.x;
    int tid = threadIdx.x;

    if (tid < 32) {
        float acc = 0.0f;
        #pragma unroll
        for (int t = 0; t < 15; t++) acc += theta[c * 15 + t] * Bp.B[tid][t];
        if (tid & 1) sb[tid >> 1] = acc;
        else         sa[tid >> 1] = acc;
    }
    if (tid >= 32 && tid < 32 + 15)
        theta_out[c * 15 + (tid - 32)] = theta[c * 15 + (tid - 32)];
    __syncthreads();

    float tm  = (float)(*time_p);
    float dt  = tm / 10.0f;
    float ddt = dt / 5.0f;

    if (tid < 16) {
        float a = sa[tid], b = sb[tid];
        float eta = expf(dt * a);
        bool  nz  = fabsf(a) > 1e-7f;
        sE[tid] = nz ? eta : 1.0f;
        sK[tid] = nz ? (b / a) * (eta - 1.0f) : b * dt;
    }
    __syncthreads();

    // Samples 0..512: thread i handles sample i; thread 0 also sample 512.
    for (int i = tid; i <= M_SAMP; i += 512) {
        float phi = (float)i / (float)M_SAMP;
        float x0  = phi;
        #pragma unroll 1
        for (int s = 0; s < 10; s++) {
            int   c0 = cellf(phi);
            float pc = fmaf(sE[c0], phi, sK[c0]);
            if (cellf(pc) == c0) {
                phi = pc;
            } else {
                float p = phi;
                #pragma unroll
                for (int e = 0; e < 5; e++) {
                    int   cc = cellf(p);
                    float v  = fmaf(sa[cc], p, sb[cc]);
                    p = fmaf(ddt, v, p);
                }
                phi = p;
            }
        }
        // y = phi*6 - 3 ; node X = x0*6 - 3 ; displacement d = (phi - x0)*6
        sd[i] = (phi - x0) * 6.0f;
    }
    __syncthreads();

    for (int i = tid; i < M_SAMP; i += 512)
        g_tabh[c * TAB_W + i] = __floats2half2_rn(sd[i], sd[i + 1]);
}

// ----------------------------------------------------------------------------
// Main pass: float4 LDG/STG (4 wavefronts/warp-op), one LDS.32 per element,
// branch-free clamped lerp (LDS always in-bounds; FSEL picks identity for
// out-of-domain |xv| >= 3). PDL: sync on the build grid before reading table.
// ----------------------------------------------------------------------------
__device__ __forceinline__ float lerp_tab(const __half2* __restrict__ tb, float xv) {
    // t = (xv + 3)/6 * M_SAMP, folded into one fma
    float t = fmaf(xv, (float)M_SAMP / 6.0f, (float)M_SAMP * 0.5f);
    t = fminf(fmaxf(t, 0.0f), 511.99996948f);   // largest float < 512
    int   i  = (int)t;                           // trunc == floor (t >= 0)
    float fr = t - (float)i;
    float2 d = __half22float2(tb[i]);            // (d_i, d_{i+1})
    float r  = xv + fmaf(d.y - d.x, fr, d.x);
    return (fabsf(xv) < 3.0f) ? r : xv;
}

__global__ void __launch_bounds__(1024, 2) cpab_main_kernel(
        const float4* __restrict__ x4,
        float4* __restrict__ out4,
        int N, int C4) {
    extern __shared__ __half2 s_tab[];            // 32 * 513 * 4B = 65.7 KB

    // PDL: wait for the build kernel (implicit completion trigger) before
    // touching g_tabh. Everything above this point overlaps with build.
    cudaGridDependencySynchronize();

    int c0 = blockIdx.x * CH_PER_BLK;
    {
        const float4* src = (const float4*)(g_tabh + c0 * TAB_W);
        float4*       dst = (float4*)s_tab;
        int n4 = CH_PER_BLK * TAB_W / 4;          // 16416/4 = 4104, exact
        for (int i = threadIdx.x; i < n4; i += blockDim.x)
            dst[i] = src[i];
    }
    __syncthreads();

    int p   = threadIdx.x & 7;                    // which float4 of 32 ch
    int row = threadIdx.x >> 3;                   // 0..127
    const __half2* tb = s_tab + p * 4 * TAB_W;

    int vbase = blockIdx.x * 8 + p;               // float4 column index

    int rows_per = (N + gridDim.y - 1) / gridDim.y;
    int r0 = blockIdx.y * rows_per;
    int r1 = min(r0 + rows_per, N);

    #pragma unroll 4
    for (int r = r0 + row; r < r1; r += 128) {
        size_t idx = (size_t)r * C4 + vbase;
        float4 v = __ldcs(&x4[idx]);
        float4 o;
        o.x = lerp_tab(tb + 0 * TAB_W, v.x);
        o.y = lerp_tab(tb + 1 * TAB_W, v.y);
        o.z = lerp_tab(tb + 2 * TAB_W, v.z);
        o.w = lerp_tab(tb + 3 * TAB_W, v.w);
        __stcs(&out4[idx], o);
    }
}

// ----------------------------------------------------------------------------
// Launch: inputs = [x, edge_index, edge_attr, batch, time, theta]
// output = concat(out[N,C], theta[C,15]) as float32
// ----------------------------------------------------------------------------
extern "C" void kernel_launch(void* const* d_in, const int* in_sizes, int n_in,
                              void* d_out, int out_size) {
    const float* x      = (const float*)d_in[0];
    const int*   time_p = (const int*)d_in[4];
    const float* theta  = (const float*)d_in[5];

    int C = in_sizes[5] / 15;   // 256
    int N = in_sizes[0] / C;    // 131072

    BParam Bp;
    compute_basis(Bp.B);

    // One integration chain per thread: build critical path ~= 1 sample.
    build_tab_kernel<<<C, 512>>>(theta, time_p,
                                 (float*)d_out + (size_t)N * C, Bp);

    const int smem_bytes = CH_PER_BLK * TAB_W * (int)sizeof(__half2); // 65664
    cudaFuncSetAttribute(cpab_main_kernel,
                         cudaFuncAttributeMaxDynamicSharedMemorySize,
                         smem_bytes);

    // Single wave: 2 blocks/SM (1024 thr, 65.7 KB smem, 32 regs) x 148 SMs
    // = 296 slots; grid 8 x 37 = 296 blocks.
    dim3 grid(C / CH_PER_BLK, 37);

    // Programmatic dependent launch: main's blocks are scheduled while the
    // build kernel still runs; cudaGridDependencySynchronize() inside the
    // kernel provides the ordering + memory visibility.
    cudaLaunchConfig_t cfg = {};
    cfg.gridDim          = grid;
    cfg.blockDim         = dim3(1024, 1, 1);
    cfg.dynamicSmemBytes = (size_t)smem_bytes;
    cfg.stream           = 0;                     // legacy stream (captured)
    cudaLaunchAttribute attrs[1];
    attrs[0].id = cudaLaunchAttributeProgrammaticStreamSerialization;
    attrs[0].val.programmaticStreamSerializationAllowed = 1;
    cfg.attrs    = attrs;
    cfg.numAttrs = 1;

    cudaLaunchKernelEx(&cfg, cpab_main_kernel,
                       (const float4*)x, (float4*)d_out, N, C / 4);
}

// round 12
// speedup vs baseline: 1.0094x; 1.0094x over previous
#include <cuda_runtime.h>
#include <cuda_fp16.h>
#include <cstring>
#include <cmath>

// ============================================================================
// CPAB activation (difw Tessellation, NC=16 cells, RADIUS=3, 10x5 integration)
//
// out[n,c] = f_c(x[n,c]) where f_c is piecewise-LINEAR in x0. Strategy:
//   1) host: B_BASIS = last 15 rows of Q from Householder LQ of the 17x32
//      constraint matrix (matches numpy dgesdd Path 4t null-space rows).
//   2) gpu:  build per-channel LUT with the exact reference integrator,
//      stored as half2 (d_i, delta_i) displacement pairs, d = f(X)-X.
//      KEY: the CPA constraints force b_0 = 0 and a_15+b_15 = 0, so x=0/x=1
//      are exact fixed points -> d_0 = d_512 = 0. Hence the index CLAMP alone
//      implements the out-of-domain identity (xv <= -3 -> fr=0,d=0 -> r=xv;
//      xv >= 3 -> r = xv + d_511*3e-5 ~ xv). No fabs/select needed.
//   3) gpu:  float4 streaming pass, 32 channels (=128B) per block row,
//      4 wavefronts per LDG.128/STG.128, one LDS.32 + 2 fma per element,
//      1024 thr/block, 65.7KB dynamic smem, 2 blocks/SM, single wave, PDL.
// ============================================================================

#define M_SAMP      512
#define TAB_W       (M_SAMP + 1)          // word stride per channel (odd)
#define CH_PER_BLK  32
#define MAX_C       256

struct BParam { float B[32][15]; };

// Packed table: word i of channel c = half2(d_i, d_{i+1} - d_i).
__device__ __half2 g_tabh[MAX_C * TAB_W];

// ----------------------------------------------------------------------------
// Host: B_BASIS via Householder LQ (float64), matching LAPACK DGELQF/DORGLQ.
// ----------------------------------------------------------------------------
static void compute_basis(float Bout[32][15]) {
    const int nc = 16;
    const int m = nc + 1;      // 17
    const int n = 2 * nc;      // 32
    double A[17][32];
    std::memset(A, 0, sizeof(A));
    for (int k = 1; k < nc; k++) {
        double xk = (double)k / (double)nc;
        A[k - 1][2 * (k - 1)]     =  xk;
        A[k - 1][2 * (k - 1) + 1] =  1.0;
        A[k - 1][2 * k]           = -xk;
        A[k - 1][2 * k + 1]       = -1.0;
    }
    A[nc - 1][1]         = 1.0;
    A[nc][2 * (nc - 1)]  = 1.0;
    A[nc][2 * nc - 1]    = 1.0;

    double tau[17];
    for (int i = 0; i < m; i++) {
        double xn2 = 0.0;
        for (int j = i + 1; j < n; j++) xn2 += A[i][j] * A[i][j];
        double alpha = A[i][i];
        if (xn2 == 0.0) { tau[i] = 0.0; continue; }
        double beta = -copysign(sqrt(alpha * alpha + xn2), alpha);
        tau[i] = (beta - alpha) / beta;
        double s = 1.0 / (alpha - beta);
        for (int j = i + 1; j < n; j++) A[i][j] *= s;
        A[i][i] = beta;
        for (int r = i + 1; r < m; r++) {
            double w = A[r][i];
            for (int j = i + 1; j < n; j++) w += A[r][j] * A[i][j];
            w *= tau[i];
            A[r][i] -= w;
            for (int j = i + 1; j < n; j++) A[r][j] -= w * A[i][j];
        }
    }
    for (int t = 0; t < 15; t++) {
        double q[32];
        for (int j = 0; j < n; j++) q[j] = 0.0;
        q[m + t] = 1.0;
        for (int i = m - 1; i >= 0; i--) {
            if (tau[i] == 0.0) continue;
            double w = q[i];
            for (int j = i + 1; j < n; j++) w += A[i][j] * q[j];
            w *= tau[i];
            q[i] -= w;
            for (int j = i + 1; j < n; j++) q[j] -= w * A[i][j];
        }
        for (int j = 0; j < n; j++) Bout[j][t] = (float)q[j];
    }
}

// ----------------------------------------------------------------------------
// Device
// ----------------------------------------------------------------------------
__device__ __forceinline__ int cellf(float x) {
    int c = __float2int_rd(x * 16.0f);
    return min(max(c, 0), 15);
}

// One block per channel, 512 threads: a,b from theta @ B^T, exact reference
// integration -- one grid sample per thread (tid 0 also takes node 512).
__global__ void __launch_bounds__(512) build_tab_kernel(
        const float* __restrict__ theta,
        const int* __restrict__ time_p,
        float* __restrict__ theta_out,
        BParam Bp) {
    __shared__ float sa[16], sb[16], sE[16], sK[16];
    __shared__ float sd[M_SAMP + 1];        // displacements d_i (fp32)
    int c = blockIdx.x;
    int tid = threadIdx.x;

    if (tid < 32) {
        float acc = 0.0f;
        #pragma unroll
        for (int t = 0; t < 15; t++) acc += theta[c * 15 + t] * Bp.B[tid][t];
        if (tid & 1) sb[tid >> 1] = acc;
        else         sa[tid >> 1] = acc;
    }
    if (tid >= 32 && tid < 32 + 15)
        theta_out[c * 15 + (tid - 32)] = theta[c * 15 + (tid - 32)];
    __syncthreads();

    float tm  = (float)(*time_p);
    float dt  = tm / 10.0f;
    float ddt = dt / 5.0f;

    if (tid < 16) {
        float a = sa[tid], b = sb[tid];
        float eta = expf(dt * a);
        bool  nz  = fabsf(a) > 1e-7f;
        sE[tid] = nz ? eta : 1.0f;
        sK[tid] = nz ? (b / a) * (eta - 1.0f) : b * dt;
    }
    __syncthreads();

    // Samples 0..512: thread i handles sample i; thread 0 also sample 512.
    for (int i = tid; i <= M_SAMP; i += 512) {
        float phi = (float)i / (float)M_SAMP;
        float x0  = phi;
        #pragma unroll 1
        for (int s = 0; s < 10; s++) {
            int   c0 = cellf(phi);
            float pc = fmaf(sE[c0], phi, sK[c0]);
            if (cellf(pc) == c0) {
                phi = pc;
            } else {
                float p = phi;
                #pragma unroll
                for (int e = 0; e < 5; e++) {
                    int   cc = cellf(p);
                    float v  = fmaf(sa[cc], p, sb[cc]);
                    p = fmaf(ddt, v, p);
                }
                phi = p;
            }
        }
        // Displacement d = (f(x0) - x0) * 6. Boundary nodes are exact fixed
        // points (b_0 = 0, a_15+b_15 = 0) -> force d = 0 exactly so the
        // clamped lerp yields identity out of domain.
        float d = (i == 0 || i == M_SAMP) ? 0.0f : (phi - x0) * 6.0f;
        sd[i] = d;
    }
    __syncthreads();

    for (int i = tid; i < M_SAMP; i += 512)
        g_tabh[c * TAB_W + i] = __floats2half2_rn(sd[i], sd[i + 1] - sd[i]);
}

// ----------------------------------------------------------------------------
// Main pass: float4 LDG/STG (4 wavefronts/warp-op); per element:
// 1 fma (index) + 2 clamp + cvt + 1 LDS.32 + cvt + 1 fma + 1 add. The clamp
// doubles as the out-of-domain identity (boundary displacements are zero).
// ----------------------------------------------------------------------------
__device__ __forceinline__ float lerp_tab(const __half2* __restrict__ tb, float xv) {
    // t = (xv + 3)/6 * M_SAMP, folded into one fma
    float t = fmaf(xv, (float)M_SAMP / 6.0f, (float)M_SAMP * 0.5f);
    t = fminf(fmaxf(t, 0.0f), 511.99996948f);   // largest float < 512
    int   i  = (int)t;                           // trunc == floor (t >= 0)
    float fr = t - (float)i;
    float2 d = __half22float2(tb[i]);            // (d_i, delta_i)
    return xv + fmaf(d.y, fr, d.x);
}

__global__ void __launch_bounds__(1024, 2) cpab_main_kernel(
        const float4* __restrict__ x4,
        float4* __restrict__ out4,
        int N, int C4) {
    extern __shared__ __half2 s_tab[];            // 32 * 513 * 4B = 65.7 KB

    // PDL: wait for the build kernel before touching g_tabh.
    cudaGridDependencySynchronize();

    int c0 = blockIdx.x * CH_PER_BLK;
    {
        const float4* src = (const float4*)(g_tabh + c0 * TAB_W);
        float4*       dst = (float4*)s_tab;
        int n4 = CH_PER_BLK * TAB_W / 4;          // 16416/4 = 4104, exact
        for (int i = threadIdx.x; i < n4; i += blockDim.x)
            dst[i] = src[i];
    }
    __syncthreads();

    int p   = threadIdx.x & 7;                    // which float4 of 32 ch
    int row = threadIdx.x >> 3;                   // 0..127
    const __half2* tb = s_tab + p * 4 * TAB_W;

    int vbase = blockIdx.x * 8 + p;               // float4 column index

    int rows_per = (N + gridDim.y - 1) / gridDim.y;
    int r0 = blockIdx.y * rows_per;
    int r1 = min(r0 + rows_per, N);

    #pragma unroll 4
    for (int r = r0 + row; r < r1; r += 128) {
        size_t idx = (size_t)r * C4 + vbase;
        float4 v = __ldcs(&x4[idx]);
        float4 o;
        o.x = lerp_tab(tb + 0 * TAB_W, v.x);
        o.y = lerp_tab(tb + 1 * TAB_W, v.y);
        o.z = lerp_tab(tb + 2 * TAB_W, v.z);
        o.w = lerp_tab(tb + 3 * TAB_W, v.w);
        __stcs(&out4[idx], o);
    }
}

// ----------------------------------------------------------------------------
// Launch: inputs = [x, edge_index, edge_attr, batch, time, theta]
// output = concat(out[N,C], theta[C,15]) as float32
// ----------------------------------------------------------------------------
extern "C" void kernel_launch(void* const* d_in, const int* in_sizes, int n_in,
                              void* d_out, int out_size) {
    const float* x      = (const float*)d_in[0];
    const int*   time_p = (const int*)d_in[4];
    const float* theta  = (const float*)d_in[5];

    int C = in_sizes[5] / 15;   // 256
    int N = in_sizes[0] / C;    // 131072

    BParam Bp;
    compute_basis(Bp.B);

    // One integration chain per thread: build critical path ~= 1 sample.
    build_tab_kernel<<<C, 512>>>(theta, time_p,
                                 (float*)d_out + (size_t)N * C, Bp);

    const int smem_bytes = CH_PER_BLK * TAB_W * (int)sizeof(__half2); // 65664
    cudaFuncSetAttribute(cpab_main_kernel,
                         cudaFuncAttributeMaxDynamicSharedMemorySize,
                         smem_bytes);

    // Single wave: 2 blocks/SM (1024 thr, 65.7 KB smem, 32 regs) x 148 SMs
    // = 296 slots; grid 8 x 37 = 296 blocks.
    dim3 grid(C / CH_PER_BLK, 37);

    cudaLaunchConfig_t cfg = {};
    cfg.gridDim          = grid;
    cfg.blockDim         = dim3(1024, 1, 1);
    cfg.dynamicSmemBytes = (size_t)smem_bytes;
    cfg.stream           = 0;
    cudaLaunchAttribute attrs[1];
    attrs[0].id = cudaLaunchAttributeProgrammaticStreamSerialization;
    attrs[0].val.programmaticStreamSerializationAllowed = 1;
    cfg.attrs    = attrs;
    cfg.numAttrs = 1;

    cudaLaunchKernelEx(&cfg, cpab_main_kernel,
                       (const float4*)x, (float4*)d_out, N, C / 4);
}